// round 10
// baseline (speedup 1.0000x reference)
#include <cuda_runtime.h>
#include <cuda_bf16.h>

// Problem constants (fixed by the reference setup)
constexpr int B        = 16;
constexpr int H        = 16;
constexpr int D        = 128;
constexpr int BS       = 16;    // tokens per physical KV block
constexpr int BPS      = 128;   // blocks per sequence
constexpr int NSPLIT   = 4;
constexpr int CHUNK    = 512;   // tokens per split (NSPLIT*CHUNK = 2048)
constexpr int NW       = 8;     // warps per CTA
constexpr int THREADS  = NW * 32;

// Scratch for split-KV partials (no cudaMalloc allowed)
__device__ float  g_part_acc[B * H * NSPLIT * D];   // 512 KB
__device__ float2 g_part_ml [B * H * NSPLIT];       // (m, l) per partial

__device__ __forceinline__ float warp_sum(float v) {
    v += __shfl_xor_sync(0xffffffffu, v, 16);
    v += __shfl_xor_sync(0xffffffffu, v, 8);
    v += __shfl_xor_sync(0xffffffffu, v, 4);
    v += __shfl_xor_sync(0xffffffffu, v, 2);
    v += __shfl_xor_sync(0xffffffffu, v, 1);
    return v;
}
__device__ __forceinline__ float warp_max(float v) {
    v = fmaxf(v, __shfl_xor_sync(0xffffffffu, v, 16));
    v = fmaxf(v, __shfl_xor_sync(0xffffffffu, v, 8));
    v = fmaxf(v, __shfl_xor_sync(0xffffffffu, v, 4));
    v = fmaxf(v, __shfl_xor_sync(0xffffffffu, v, 2));
    v = fmaxf(v, __shfl_xor_sync(0xffffffffu, v, 1));
    return v;
}

// ---------------------------------------------------------------------------
// Kernel 1: per-(b,h,split) partial attention, two-pass (R3 structure),
// 512-token chunks (1024 CTAs = single wave, halved per-item overhead).
// ---------------------------------------------------------------------------
__global__ __launch_bounds__(THREADS)
void pa_split_kernel(const float* __restrict__ q,
                     const float* __restrict__ kc,
                     const float* __restrict__ vc,
                     const int*   __restrict__ bt,
                     const int*   __restrict__ cl)
{
    __shared__ float  sc[CHUNK];              // 2 KB score buffer
    __shared__ float4 wacc4[NW][D / 4];       // 4 KB
    __shared__ int    sblk[CHUNK / BS];       // 32 block ids
    __shared__ float  red[NW];
    __shared__ float  s_m;

    const int tid  = threadIdx.x;
    const int lane = tid & 31;
    const int wid  = tid >> 5;

    const int s  = blockIdx.x & (NSPLIT - 1);
    const int bh = blockIdx.x >> 2;          // b*H + h
    const int b  = bh >> 4;
    const int h  = bh & 15;

    const int ctx   = cl[b];
    const int t0    = s * CHUNK;
    const int pbase = bh * NSPLIT + s;

    int n = ctx - t0;
    if (n <= 0) return;                       // inactive: combine skips us
    if (n > CHUNK) n = CHUNK;

    if (tid < CHUNK / BS)
        sblk[tid] = bt[b * BPS + s * (CHUNK / BS) + tid];

    const float4 q4 = reinterpret_cast<const float4*>(q + (size_t)bh * D)[lane];
    __syncthreads();

    const float scale = 0.08838834764831845f;   // 1/sqrt(128)

    // ---- Pass 1: scores (guarded, MLP=2 per warp — the R3 winner) ----------
    for (int t = wid; t < n; t += 2 * NW) {
        const int t2    = t + NW;
        const bool has2 = (t2 < n);

        const float* kp1 = kc + ((((size_t)sblk[t >> 4] * BS + (t & 15)) * H + h) * D);
        float4 k1 = reinterpret_cast<const float4*>(kp1)[lane];

        float4 k2 = make_float4(0.f, 0.f, 0.f, 0.f);
        if (has2) {
            const float* kp2 = kc + ((((size_t)sblk[t2 >> 4] * BS + (t2 & 15)) * H + h) * D);
            k2 = reinterpret_cast<const float4*>(kp2)[lane];
        }

        float d1 = k1.x * q4.x + k1.y * q4.y + k1.z * q4.z + k1.w * q4.w;
        float d2 = k2.x * q4.x + k2.y * q4.y + k2.z * q4.z + k2.w * q4.w;

        d1 = warp_sum(d1);
        if (has2) d2 = warp_sum(d2);

        if (lane == 0) {
            sc[t] = d1 * scale;
            if (has2) sc[t2] = d2 * scale;
        }
    }
    __syncthreads();

    // ---- Block softmax over the chunk (2 scores per thread) ----------------
    const int tidB = tid + THREADS;
    const float v1 = (tid  < n) ? sc[tid]  : -3.0e38f;
    const float v2 = (tidB < n) ? sc[tidB] : -3.0e38f;

    float m = warp_max(fmaxf(v1, v2));
    if (lane == 0) red[wid] = m;
    __syncthreads();
    if (wid == 0) {
        float x = (lane < NW) ? red[lane] : -3.0e38f;
        x = warp_max(x);
        if (lane == 0) s_m = x;
    }
    __syncthreads();
    const float M = s_m;

    const float p1 = (tid  < n) ? __expf(v1 - M) : 0.0f;
    const float p2 = (tidB < n) ? __expf(v2 - M) : 0.0f;
    sc[tid]  = p1;                 // masked slots get 0
    sc[tidB] = p2;

    float l = warp_sum(p1 + p2);
    if (lane == 0) red[wid] = l;
    __syncthreads();

    // ---- Pass 2: weighted V accumulation ------------------------------------
    float4 acc = make_float4(0.f, 0.f, 0.f, 0.f);
    #pragma unroll 2
    for (int t = wid; t < n; t += NW) {
        const float pt = sc[t];
        const float* vp = vc + ((((size_t)sblk[t >> 4] * BS + (t & 15)) * H + h) * D);
        const float4 v4 = reinterpret_cast<const float4*>(vp)[lane];
        acc.x += pt * v4.x;
        acc.y += pt * v4.y;
        acc.z += pt * v4.z;
        acc.w += pt * v4.w;
    }
    wacc4[wid][lane] = acc;
    __syncthreads();

    if (tid < D) {
        const float* wf = reinterpret_cast<const float*>(wacc4);
        float o = 0.0f;
        #pragma unroll
        for (int w = 0; w < NW; ++w) o += wf[w * D + tid];
        g_part_acc[pbase * D + tid] = o;
    }
    if (tid == 0) {
        float L = 0.0f;
        #pragma unroll
        for (int w = 0; w < NW; ++w) L += red[w];
        g_part_ml[pbase] = make_float2(M, L);
    }
}

// ---------------------------------------------------------------------------
// Kernel 2: ctx-aware combine, launched with PDL. Independent setup (indices,
// context length) runs while the split kernel is still executing; the grid
// dependency sync gates only the partial reads.
// ---------------------------------------------------------------------------
__global__ __launch_bounds__(D)
void pa_combine_kernel(const int* __restrict__ cl, float* __restrict__ out)
{
    const int bh = blockIdx.x;
    const int d  = threadIdx.x;
    const int b  = bh >> 4;

    int ctx = cl[b];                    // input buffer: safe pre-sync
    if (ctx > NSPLIT * CHUNK) ctx = NSPLIT * CHUNK;
    const int n_act = (ctx + CHUNK - 1) / CHUNK;   // >= 1

#if __CUDA_ARCH__ >= 900
    cudaGridDependencySynchronize();    // wait for split kernel's writes
#endif

    float2 ml[NSPLIT];
    #pragma unroll
    for (int s = 0; s < NSPLIT; ++s)
        ml[s] = (s < n_act) ? g_part_ml[bh * NSPLIT + s]
                            : make_float2(-3.0e38f, 0.0f);

    float M = -3.0e38f;
    #pragma unroll
    for (int s = 0; s < NSPLIT; ++s) M = fmaxf(M, ml[s].x);

    float av[NSPLIT];
    #pragma unroll
    for (int s = 0; s < NSPLIT; ++s)
        av[s] = (s < n_act) ? g_part_acc[(bh * NSPLIT + s) * D + d] : 0.0f;

    float L = 0.0f, o = 0.0f;
    #pragma unroll
    for (int s = 0; s < NSPLIT; ++s) {
        const float f = __expf(ml[s].x - M);
        L += ml[s].y * f;
        o += av[s] * f;
    }
    out[bh * D + d] = o / L;
}

extern "C" void kernel_launch(void* const* d_in, const int* in_sizes, int n_in,
                              void* d_out, int out_size)
{
    const float* q  = (const float*)d_in[0];
    const float* kc = (const float*)d_in[1];
    const float* vc = (const float*)d_in[2];
    const int*   bt = (const int*)d_in[3];
    const int*   cl = (const int*)d_in[4];
    float* out = (float*)d_out;

    pa_split_kernel<<<B * H * NSPLIT, THREADS>>>(q, kc, vc, bt, cl);

    // PDL: combine may launch while split is resident; it self-synchronizes.
    cudaLaunchAttribute attrs[1];
    attrs[0].id = cudaLaunchAttributeProgrammaticStreamSerialization;
    attrs[0].val.programmaticStreamSerializationAllowed = 1;

    cudaLaunchConfig_t cfg = {};
    cfg.gridDim  = dim3(B * H, 1, 1);
    cfg.blockDim = dim3(D, 1, 1);
    cfg.dynamicSmemBytes = 0;
    cfg.stream = 0;
    cfg.attrs = attrs;
    cfg.numAttrs = 1;
    cudaLaunchKernelEx(&cfg, pa_combine_kernel, cl, out);
}

// round 11
// speedup vs baseline: 1.0381x; 1.0381x over previous
#include <cuda_runtime.h>
#include <cuda_bf16.h>

// Problem constants (fixed by the reference setup)
constexpr int B        = 16;
constexpr int H        = 16;
constexpr int D        = 128;
constexpr int BS       = 16;    // tokens per physical KV block
constexpr int BPS      = 128;   // blocks per sequence
constexpr int NSPLIT   = 8;
constexpr int CHUNK    = 256;   // tokens per split (verified optimum)
constexpr int NW       = 8;     // warps per CTA
constexpr int THREADS  = NW * 32;

// Scratch for split-KV partials (no cudaMalloc allowed)
__device__ float  g_part_acc[B * H * NSPLIT * D];   // 1 MB
__device__ float2 g_part_ml [B * H * NSPLIT];       // (m, l) per partial

__device__ __forceinline__ float warp_sum(float v) {
    v += __shfl_xor_sync(0xffffffffu, v, 16);
    v += __shfl_xor_sync(0xffffffffu, v, 8);
    v += __shfl_xor_sync(0xffffffffu, v, 4);
    v += __shfl_xor_sync(0xffffffffu, v, 2);
    v += __shfl_xor_sync(0xffffffffu, v, 1);
    return v;
}
__device__ __forceinline__ float warp_max(float v) {
    v = fmaxf(v, __shfl_xor_sync(0xffffffffu, v, 16));
    v = fmaxf(v, __shfl_xor_sync(0xffffffffu, v, 8));
    v = fmaxf(v, __shfl_xor_sync(0xffffffffu, v, 4));
    v = fmaxf(v, __shfl_xor_sync(0xffffffffu, v, 2));
    v = fmaxf(v, __shfl_xor_sync(0xffffffffu, v, 1));
    return v;
}

__device__ __forceinline__ void prefetch_l2(const void* p) {
    asm volatile("prefetch.global.L2 [%0];" :: "l"(p));
}

// ---------------------------------------------------------------------------
// Kernel 1: per-(b,h,split) partial attention, two-pass (R3 structure,
// CHUNK=256 verified optimum). Pass 1 additionally prefetches each token's
// V row to L2 (same offset, vc base), so pass 2 hits L2 instead of DRAM and
// the K/V DRAM streams overlap. Ends with a PDL trigger.
// ---------------------------------------------------------------------------
__global__ __launch_bounds__(THREADS)
void pa_split_kernel(const float* __restrict__ q,
                     const float* __restrict__ kc,
                     const float* __restrict__ vc,
                     const int*   __restrict__ bt,
                     const int*   __restrict__ cl)
{
    __shared__ float  sc[CHUNK];
    __shared__ float4 wacc4[NW][D / 4];       // 4 KB
    __shared__ int    sblk[CHUNK / BS];
    __shared__ float  red[NW];
    __shared__ float  s_m;

    const int tid  = threadIdx.x;
    const int lane = tid & 31;
    const int wid  = tid >> 5;

    const int s  = blockIdx.x & (NSPLIT - 1);
    const int bh = blockIdx.x >> 3;          // b*H + h
    const int b  = bh >> 4;
    const int h  = bh & 15;

    const int ctx   = cl[b];
    const int t0    = s * CHUNK;
    const int pbase = bh * NSPLIT + s;

    int n = ctx - t0;
    if (n <= 0) return;                       // inactive: combine skips us
    if (n > CHUNK) n = CHUNK;

    if (tid < CHUNK / BS)
        sblk[tid] = bt[b * BPS + s * (CHUNK / BS) + tid];

    const float4 q4 = reinterpret_cast<const float4*>(q + (size_t)bh * D)[lane];
    __syncthreads();

    const float scale = 0.08838834764831845f;   // 1/sqrt(128)

    // ---- Pass 1: scores (guarded, MLP=2) + V prefetch to L2 ---------------
    for (int t = wid; t < n; t += 2 * NW) {
        const int t2    = t + NW;
        const bool has2 = (t2 < n);

        const size_t off1 = (((size_t)sblk[t >> 4] * BS + (t & 15)) * H + h) * D;
        float4 k1 = reinterpret_cast<const float4*>(kc + off1)[lane];
        prefetch_l2(reinterpret_cast<const float4*>(vc + off1) + lane);

        float4 k2 = make_float4(0.f, 0.f, 0.f, 0.f);
        if (has2) {
            const size_t off2 = (((size_t)sblk[t2 >> 4] * BS + (t2 & 15)) * H + h) * D;
            k2 = reinterpret_cast<const float4*>(kc + off2)[lane];
            prefetch_l2(reinterpret_cast<const float4*>(vc + off2) + lane);
        }

        float d1 = k1.x * q4.x + k1.y * q4.y + k1.z * q4.z + k1.w * q4.w;
        float d2 = k2.x * q4.x + k2.y * q4.y + k2.z * q4.z + k2.w * q4.w;

        d1 = warp_sum(d1);
        if (has2) d2 = warp_sum(d2);

        if (lane == 0) {
            sc[t] = d1 * scale;
            if (has2) sc[t2] = d2 * scale;
        }
    }
    __syncthreads();

    // ---- Block softmax over the chunk ---------------------------------------
    const float v = (tid < n) ? sc[tid] : -3.0e38f;
    float m = warp_max(v);
    if (lane == 0) red[wid] = m;
    __syncthreads();
    if (wid == 0) {
        float x = (lane < NW) ? red[lane] : -3.0e38f;
        x = warp_max(x);
        if (lane == 0) s_m = x;
    }
    __syncthreads();
    const float M = s_m;

    const float p = (tid < n) ? __expf(v - M) : 0.0f;
    sc[tid] = p;                      // masked slots get 0
    float l = warp_sum(p);
    if (lane == 0) red[wid] = l;
    __syncthreads();

    // ---- Pass 2: weighted V accumulation (L2-hot after prefetch) -----------
    float4 acc = make_float4(0.f, 0.f, 0.f, 0.f);
    #pragma unroll 2
    for (int t = wid; t < n; t += NW) {
        const float pt = sc[t];
        const float* vp = vc + ((((size_t)sblk[t >> 4] * BS + (t & 15)) * H + h) * D);
        const float4 v4 = reinterpret_cast<const float4*>(vp)[lane];
        acc.x += pt * v4.x;
        acc.y += pt * v4.y;
        acc.z += pt * v4.z;
        acc.w += pt * v4.w;
    }
    wacc4[wid][lane] = acc;
    __syncthreads();

    if (tid < D) {
        const float* wf = reinterpret_cast<const float*>(wacc4);
        float o = 0.0f;
        #pragma unroll
        for (int w = 0; w < NW; ++w) o += wf[w * D + tid];
        g_part_acc[pbase * D + tid] = o;
    }
    if (tid == 0) {
        float L = 0.0f;
        #pragma unroll
        for (int w = 0; w < NW; ++w) L += red[w];
        g_part_ml[pbase] = make_float2(M, L);
    }

#if __CUDA_ARCH__ >= 900
    // Writes done: allow the PDL-dependent combine kernel to proceed.
    cudaTriggerProgrammaticLaunchCompletion();
#endif
}

// ---------------------------------------------------------------------------
// Kernel 2: ctx-aware combine under PDL. Prologue (index math, ctx load)
// runs concurrently with the split kernel's drain; gridsync gates only the
// partial reads.
// ---------------------------------------------------------------------------
__global__ __launch_bounds__(D)
void pa_combine_kernel(const int* __restrict__ cl, float* __restrict__ out)
{
    const int bh = blockIdx.x;
    const int d  = threadIdx.x;
    const int b  = bh >> 4;

    int ctx = cl[b];                    // harness input: safe pre-sync
    if (ctx > NSPLIT * CHUNK) ctx = NSPLIT * CHUNK;
    const int n_act = (ctx + CHUNK - 1) / CHUNK;   // >= 1

#if __CUDA_ARCH__ >= 900
    cudaGridDependencySynchronize();    // split kernel's writes now visible
#endif

    float2 ml[NSPLIT];
    #pragma unroll
    for (int s = 0; s < NSPLIT; ++s)
        ml[s] = (s < n_act) ? g_part_ml[bh * NSPLIT + s]
                            : make_float2(-3.0e38f, 0.0f);

    float M = -3.0e38f;
    #pragma unroll
    for (int s = 0; s < NSPLIT; ++s) M = fmaxf(M, ml[s].x);

    float av[NSPLIT];
    #pragma unroll
    for (int s = 0; s < NSPLIT; ++s)
        av[s] = (s < n_act) ? g_part_acc[(bh * NSPLIT + s) * D + d] : 0.0f;

    float L = 0.0f, o = 0.0f;
    #pragma unroll
    for (int s = 0; s < NSPLIT; ++s) {
        const float f = __expf(ml[s].x - M);
        L += ml[s].y * f;
        o += av[s] * f;
    }
    out[bh * D + d] = o / L;
}

extern "C" void kernel_launch(void* const* d_in, const int* in_sizes, int n_in,
                              void* d_out, int out_size)
{
    const float* q  = (const float*)d_in[0];
    const float* kc = (const float*)d_in[1];
    const float* vc = (const float*)d_in[2];
    const int*   bt = (const int*)d_in[3];
    const int*   cl = (const int*)d_in[4];
    float* out = (float*)d_out;

    pa_split_kernel<<<B * H * NSPLIT, THREADS>>>(q, kc, vc, bt, cl);

    // PDL: combine launches while split drains; it self-synchronizes.
    cudaLaunchAttribute attrs[1];
    attrs[0].id = cudaLaunchAttributeProgrammaticStreamSerialization;
    attrs[0].val.programmaticStreamSerializationAllowed = 1;

    cudaLaunchConfig_t cfg = {};
    cfg.gridDim  = dim3(B * H, 1, 1);
    cfg.blockDim = dim3(D, 1, 1);
    cfg.dynamicSmemBytes = 0;
    cfg.stream = 0;
    cfg.attrs = attrs;
    cfg.numAttrs = 1;
    cudaLaunchKernelEx(&cfg, pa_combine_kernel, cl, out);
}

// round 12
// speedup vs baseline: 1.2957x; 1.2481x over previous
#include <cuda_runtime.h>
#include <cuda_bf16.h>

// Problem constants (fixed by the reference setup)
constexpr int B        = 16;
constexpr int H        = 16;
constexpr int D        = 128;
constexpr int BS       = 16;    // tokens per physical KV block
constexpr int BPS      = 128;   // blocks per sequence
constexpr int NSPLIT   = 8;
constexpr int CHUNK    = 256;   // tokens per split (verified optimum)
constexpr int NW       = 8;     // warps per CTA
constexpr int THREADS  = NW * 32;

// Scratch for split-KV partials (no cudaMalloc allowed)
__device__ float  g_part_acc[B * H * NSPLIT * D];   // 1 MB
__device__ float2 g_part_ml [B * H * NSPLIT];       // (m, l) per partial

__device__ __forceinline__ float warp_sum(float v) {
    v += __shfl_xor_sync(0xffffffffu, v, 16);
    v += __shfl_xor_sync(0xffffffffu, v, 8);
    v += __shfl_xor_sync(0xffffffffu, v, 4);
    v += __shfl_xor_sync(0xffffffffu, v, 2);
    v += __shfl_xor_sync(0xffffffffu, v, 1);
    return v;
}
__device__ __forceinline__ float warp_max(float v) {
    v = fmaxf(v, __shfl_xor_sync(0xffffffffu, v, 16));
    v = fmaxf(v, __shfl_xor_sync(0xffffffffu, v, 8));
    v = fmaxf(v, __shfl_xor_sync(0xffffffffu, v, 4));
    v = fmaxf(v, __shfl_xor_sync(0xffffffffu, v, 2));
    v = fmaxf(v, __shfl_xor_sync(0xffffffffu, v, 1));
    return v;
}

// ---------------------------------------------------------------------------
// Kernel 1: per-(b,h,split) partial attention, two-pass — EXACT R3 memory
// behavior (guarded MLP2, CHUNK=256, no prefetch). Only additions: ctx-aware
// early exit (combine skips inactive splits) and a PDL trigger at the end.
// ---------------------------------------------------------------------------
__global__ __launch_bounds__(THREADS)
void pa_split_kernel(const float* __restrict__ q,
                     const float* __restrict__ kc,
                     const float* __restrict__ vc,
                     const int*   __restrict__ bt,
                     const int*   __restrict__ cl)
{
    __shared__ float  sc[CHUNK];
    __shared__ float4 wacc4[NW][D / 4];       // 4 KB
    __shared__ int    sblk[CHUNK / BS];
    __shared__ float  red[NW];
    __shared__ float  s_m;

    const int tid  = threadIdx.x;
    const int lane = tid & 31;
    const int wid  = tid >> 5;

    const int s  = blockIdx.x & (NSPLIT - 1);
    const int bh = blockIdx.x >> 3;          // b*H + h
    const int b  = bh >> 4;
    const int h  = bh & 15;

    const int ctx   = cl[b];
    const int t0    = s * CHUNK;
    const int pbase = bh * NSPLIT + s;

    int n = ctx - t0;
    if (n > CHUNK) n = CHUNK;

    if (n > 0) {
        if (tid < CHUNK / BS)
            sblk[tid] = bt[b * BPS + s * (CHUNK / BS) + tid];

        const float4 q4 = reinterpret_cast<const float4*>(q + (size_t)bh * D)[lane];
        __syncthreads();

        const float scale = 0.08838834764831845f;   // 1/sqrt(128)

        // ---- Pass 1: scores (guarded, MLP=2 — the R3 winner) --------------
        for (int t = wid; t < n; t += 2 * NW) {
            const int t2    = t + NW;
            const bool has2 = (t2 < n);

            const float* kp1 = kc + ((((size_t)sblk[t >> 4] * BS + (t & 15)) * H + h) * D);
            float4 k1 = reinterpret_cast<const float4*>(kp1)[lane];

            float4 k2 = make_float4(0.f, 0.f, 0.f, 0.f);
            if (has2) {
                const float* kp2 = kc + ((((size_t)sblk[t2 >> 4] * BS + (t2 & 15)) * H + h) * D);
                k2 = reinterpret_cast<const float4*>(kp2)[lane];
            }

            float d1 = k1.x * q4.x + k1.y * q4.y + k1.z * q4.z + k1.w * q4.w;
            float d2 = k2.x * q4.x + k2.y * q4.y + k2.z * q4.z + k2.w * q4.w;

            d1 = warp_sum(d1);
            if (has2) d2 = warp_sum(d2);

            if (lane == 0) {
                sc[t] = d1 * scale;
                if (has2) sc[t2] = d2 * scale;
            }
        }
        __syncthreads();

        // ---- Block softmax over the chunk -----------------------------------
        const float v = (tid < n) ? sc[tid] : -3.0e38f;
        float m = warp_max(v);
        if (lane == 0) red[wid] = m;
        __syncthreads();
        if (wid == 0) {
            float x = (lane < NW) ? red[lane] : -3.0e38f;
            x = warp_max(x);
            if (lane == 0) s_m = x;
        }
        __syncthreads();
        const float M = s_m;

        const float p = (tid < n) ? __expf(v - M) : 0.0f;
        sc[tid] = p;                      // masked slots get 0
        float l = warp_sum(p);
        if (lane == 0) red[wid] = l;
        __syncthreads();

        // ---- Pass 2: weighted V accumulation ---------------------------------
        float4 acc = make_float4(0.f, 0.f, 0.f, 0.f);
        #pragma unroll 2
        for (int t = wid; t < n; t += NW) {
            const float pt = sc[t];
            const float* vp = vc + ((((size_t)sblk[t >> 4] * BS + (t & 15)) * H + h) * D);
            const float4 v4 = reinterpret_cast<const float4*>(vp)[lane];
            acc.x += pt * v4.x;
            acc.y += pt * v4.y;
            acc.z += pt * v4.z;
            acc.w += pt * v4.w;
        }
        wacc4[wid][lane] = acc;
        __syncthreads();

        if (tid < D) {
            const float* wf = reinterpret_cast<const float*>(wacc4);
            float o = 0.0f;
            #pragma unroll
            for (int w = 0; w < NW; ++w) o += wf[w * D + tid];
            g_part_acc[pbase * D + tid] = o;
        }
        if (tid == 0) {
            float L = 0.0f;
            #pragma unroll
            for (int w = 0; w < NW; ++w) L += red[w];
            g_part_ml[pbase] = make_float2(M, L);
        }
    }

#if __CUDA_ARCH__ >= 900
    // Writes done (or inactive): allow the PDL-dependent combine to proceed.
    cudaTriggerProgrammaticLaunchCompletion();
#endif
}

// ---------------------------------------------------------------------------
// Kernel 2: ctx-aware combine under PDL. Prologue (index math, ctx load)
// executes while the split kernel drains; gridsync gates the partial reads.
// ---------------------------------------------------------------------------
__global__ __launch_bounds__(D)
void pa_combine_kernel(const int* __restrict__ cl, float* __restrict__ out)
{
    const int bh = blockIdx.x;
    const int d  = threadIdx.x;
    const int b  = bh >> 4;

    int ctx = cl[b];                    // harness input: safe pre-sync
    if (ctx > NSPLIT * CHUNK) ctx = NSPLIT * CHUNK;
    const int n_act = (ctx + CHUNK - 1) / CHUNK;   // >= 1

#if __CUDA_ARCH__ >= 900
    cudaGridDependencySynchronize();    // split kernel's writes now visible
#endif

    float2 ml[NSPLIT];
    #pragma unroll
    for (int s = 0; s < NSPLIT; ++s)
        ml[s] = (s < n_act) ? g_part_ml[bh * NSPLIT + s]
                            : make_float2(-3.0e38f, 0.0f);

    float M = -3.0e38f;
    #pragma unroll
    for (int s = 0; s < NSPLIT; ++s) M = fmaxf(M, ml[s].x);

    float av[NSPLIT];
    #pragma unroll
    for (int s = 0; s < NSPLIT; ++s)
        av[s] = (s < n_act) ? g_part_acc[(bh * NSPLIT + s) * D + d] : 0.0f;

    float L = 0.0f, o = 0.0f;
    #pragma unroll
    for (int s = 0; s < NSPLIT; ++s) {
        const float f = __expf(ml[s].x - M);
        L += ml[s].y * f;
        o += av[s] * f;
    }
    out[bh * D + d] = o / L;
}

extern "C" void kernel_launch(void* const* d_in, const int* in_sizes, int n_in,
                              void* d_out, int out_size)
{
    const float* q  = (const float*)d_in[0];
    const float* kc = (const float*)d_in[1];
    const float* vc = (const float*)d_in[2];
    const int*   bt = (const int*)d_in[3];
    const int*   cl = (const int*)d_in[4];
    float* out = (float*)d_out;

    pa_split_kernel<<<B * H * NSPLIT, THREADS>>>(q, kc, vc, bt, cl);

    // PDL: combine launches while split drains; it self-synchronizes.
    cudaLaunchAttribute attrs[1];
    attrs[0].id = cudaLaunchAttributeProgrammaticStreamSerialization;
    attrs[0].val.programmaticStreamSerializationAllowed = 1;

    cudaLaunchConfig_t cfg = {};
    cfg.gridDim  = dim3(B * H, 1, 1);
    cfg.blockDim = dim3(D, 1, 1);
    cfg.dynamicSmemBytes = 0;
    cfg.stream = 0;
    cfg.attrs = attrs;
    cfg.numAttrs = 1;
    cudaLaunchKernelEx(&cfg, pa_combine_kernel, cl, out);
}